// round 3
// baseline (speedup 1.0000x reference)
#include <cuda_runtime.h>
#include <cstdint>
#include <cstddef>

#define BB 64      // batch
#define TT 512     // time
#define HH 256     // hidden
#define GG 1024    // 4*H
#define NCTA 128   // 16 hid-groups x 8 batch-groups

// ---------------- device scratch (static, no allocations) ----------------
__device__ float g_xg[(size_t)TT * BB * GG];   // [t*64+b][4H] gate pre-activations (row-major)
__device__ float g_y0[(size_t)BB * TT * HH];   // layer-0 output, [B][T][H]
__device__ float g_hbuf[2][BB * HH];           // ping-pong h carry, [b][hid]
__device__ float g_masks[6 * BB * HH];         // (layer,{out,h,c}) masks [B][H]
__device__ unsigned g_bar_arrive;              // monotone arrival counter (reset per layer)

// ---------------- f32x2 packed math helpers ----------------
__device__ __forceinline__ uint64_t pack2(float lo, float hi) {
    uint64_t r; asm("mov.b64 %0, {%1,%2};" : "=l"(r) : "f"(lo), "f"(hi)); return r;
}
__device__ __forceinline__ void unpack2(uint64_t v, float& lo, float& hi) {
    asm("mov.b64 {%0,%1}, %2;" : "=f"(lo), "=f"(hi) : "l"(v));
}
#define FFMA2(acc, a, b) asm("fma.rn.f32x2 %0, %1, %2, %0;" : "+l"(acc) : "l"(a), "l"(b))

// ---------------- barrier primitives (release/acquire, gpu scope) ----------------
__device__ __forceinline__ void red_add_release(unsigned* p, unsigned v) {
    asm volatile("red.release.gpu.global.add.u32 [%0], %1;" :: "l"(p), "r"(v) : "memory");
}
__device__ __forceinline__ unsigned ld_acquire(const unsigned* p) {
    unsigned v; asm volatile("ld.acquire.gpu.global.u32 %0, [%1];" : "=r"(v) : "l"(p) : "memory");
    return v;
}

// ---------------- Threefry-2x32 (JAX, partitionable) — VALIDATED bit-exact ----------------
__device__ __forceinline__ uint32_t rotl32(uint32_t x, int n) { return __funnelshift_l(x, x, n); }

__device__ __forceinline__ void tf2x32(uint32_t k0, uint32_t k1, uint32_t x0, uint32_t x1,
                                       uint32_t& o0, uint32_t& o1) {
    uint32_t ks2 = k0 ^ k1 ^ 0x1BD11BDAu;
    x0 += k0; x1 += k1;
#define TFR(r) { x0 += x1; x1 = rotl32(x1, (r)); x1 ^= x0; }
    TFR(13) TFR(15) TFR(26) TFR(6)   x0 += k1;  x1 += ks2 + 1u;
    TFR(17) TFR(29) TFR(16) TFR(24)  x0 += ks2; x1 += k0 + 2u;
    TFR(13) TFR(15) TFR(26) TFR(6)   x0 += k0;  x1 += k1 + 3u;
    TFR(17) TFR(29) TFR(16) TFR(24)  x0 += k1;  x1 += ks2 + 4u;
    TFR(13) TFR(15) TFR(26) TFR(6)   x0 += ks2; x1 += k0 + 5u;
#undef TFR
    o0 = x0; o1 = x1;
}

__global__ void compute_masks_kernel() {
    int idx = blockIdx.x * 256 + threadIdx.x;
    if (idx >= 6 * BB * HH) return;
    int l = idx / (3 * BB * HH);
    int j = (idx / (BB * HH)) % 3;
    uint32_t e = (uint32_t)(idx % (BB * HH));
    uint32_t a0, a1, b0, b1, c0, c1;
    tf2x32(0u, 42u, 0u, (uint32_t)l, a0, a1);
    tf2x32(a0, a1, 0u, (uint32_t)j, b0, b1);
    tf2x32(b0, b1, 0u, e, c0, c1);
    uint32_t bits = c0 ^ c1;
    float u = __uint_as_float((bits >> 9) | 0x3f800000u) - 1.0f;
    g_masks[idx] = (u < 0.75f) ? (1.0f / 0.75f) : 0.0f;
}

__global__ void zero_state_kernel() {
    int i = blockIdx.x * 256 + threadIdx.x;
    if (i < BB * HH) {
        g_hbuf[0][i] = 0.0f;
        g_hbuf[1][i] = 0.0f;
    }
    if (i == 0) g_bar_arrive = 0u;   // reset per layer / per replay (determinism)
}

// ---------------- big GEMM (f32x2): xg[m][g] = sum_k A[b][t][k]*W[g][k] + bih[g]+bhh[g] ----------------
// m = t*64 + b. A: [B][T][256]; W: [1024][256]. 64x64 tile, 256 threads, 4x4 per thread.
__global__ void gemm_xg_kernel(const float* __restrict__ Aext, const float* __restrict__ W,
                               const float* __restrict__ bih, const float* __restrict__ bhh,
                               int use_y0) {
    const float* A = use_y0 ? g_y0 : Aext;
    __shared__ uint64_t As2[16][65];   // (a,a) pairs
    __shared__ float Bs[16][68];
    int tid = threadIdx.x;
    int lr = tid >> 2;            // 0..63
    int lc = (tid & 3) << 2;      // 0,4,8,12
    int m = blockIdx.x * 64 + lr;
    const float* Arow = A + ((size_t)(m & 63) * TT + (size_t)(m >> 6)) * HH;
    const float* Wrow = W + (size_t)(blockIdx.y * 64 + lr) * 256;
    int tx = tid & 15, ty = tid >> 4;
    uint64_t accp[4][2];
#pragma unroll
    for (int i = 0; i < 4; i++) { accp[i][0] = 0ull; accp[i][1] = 0ull; }  // (0.f,0.f)
    for (int k0 = 0; k0 < 256; k0 += 16) {
        float4 av = *reinterpret_cast<const float4*>(Arow + k0 + lc);
        float4 wv = *reinterpret_cast<const float4*>(Wrow + k0 + lc);
        As2[lc + 0][lr] = pack2(av.x, av.x);
        As2[lc + 1][lr] = pack2(av.y, av.y);
        As2[lc + 2][lr] = pack2(av.z, av.z);
        As2[lc + 3][lr] = pack2(av.w, av.w);
        Bs[lc + 0][lr] = wv.x; Bs[lc + 1][lr] = wv.y; Bs[lc + 2][lr] = wv.z; Bs[lc + 3][lr] = wv.w;
        __syncthreads();
#pragma unroll
        for (int kk = 0; kk < 16; kk++) {
            ulonglong2 w2 = *reinterpret_cast<const ulonglong2*>(&Bs[kk][tx << 2]);
#pragma unroll
            for (int i = 0; i < 4; i++) {
                uint64_t aa = As2[kk][(ty << 2) + i];
                FFMA2(accp[i][0], w2.x, aa);
                FFMA2(accp[i][1], w2.y, aa);
            }
        }
        __syncthreads();
    }
    int n0 = blockIdx.y * 64 + (tx << 2);
    float b0 = bih[n0 + 0] + bhh[n0 + 0];
    float b1 = bih[n0 + 1] + bhh[n0 + 1];
    float b2 = bih[n0 + 2] + bhh[n0 + 2];
    float b3 = bih[n0 + 3] + bhh[n0 + 3];
#pragma unroll
    for (int i = 0; i < 4; i++) {
        int m2 = blockIdx.x * 64 + (ty << 2) + i;
        float a0, a1, a2, a3;
        unpack2(accp[i][0], a0, a1);
        unpack2(accp[i][1], a2, a3);
        float4 o = make_float4(a0 + b0, a1 + b1, a2 + b2, a3 + b3);
        *reinterpret_cast<float4*>(&g_xg[(size_t)m2 * GG + n0]) = o;
    }
}

// ---------------- persistent per-layer recurrence kernel ----------------
// 128 CTAs x 128 threads. CTA = (hgrp: 16 hids, bgrp: 8 batches).
// tid = bl*16 + hid_l  (warp spans 2 batches x 16 hids -> coalesced h/xg/y access).
__global__ void __launch_bounds__(128, 1) lstm_layer_kernel(const float* __restrict__ Whh,
                                                            float* __restrict__ yext, int layer) {
    extern __shared__ float sm[];
    float* W4 = sm;                                            // [16 hid][256 k][4 gates] = 64KB
    uint64_t* hs2 = reinterpret_cast<uint64_t*>(sm + 16 * 1024); // [8 b][258] (h,h) pairs
    const int tid = threadIdx.x;
    const int hid_l = tid & 15;
    const int bl = tid >> 4;            // 0..7
    const int hgrp = blockIdx.x & 15;
    const int bgrp = blockIdx.x >> 4;
    const int hid = hgrp * 16 + hid_l;
    const int b = bgrp * 8 + bl;

    // stage W_hh once: W4[hl][k][gate], gate order i,f,g,o (pairs (i,f),(g,o) for f32x2)
    {
        int row = tid >> 1;             // 0..63 = hl*4 + gate
        int hl = row >> 2, gate = row & 3;
        int half = tid & 1;
        const float4* src = reinterpret_cast<const float4*>(
            Whh + ((size_t)(gate << 8) + (size_t)(hgrp * 16 + hl)) * 256 + half * 128);
        float* dst = W4 + hl * 1024 + half * 512 + gate;
#pragma unroll
        for (int j = 0; j < 32; j++) {
            float4 v = __ldg(src + j);
            dst[j * 16 + 0] = v.x; dst[j * 16 + 4] = v.y;
            dst[j * 16 + 8] = v.z; dst[j * 16 + 12] = v.w;
        }
    }

    const int mi = b * HH + hid;
    const float mo  = g_masks[(layer * 3 + 0) * BB * HH + mi];
    const float mh  = g_masks[(layer * 3 + 1) * BB * HH + mi];
    const float mcm = g_masks[(layer * 3 + 2) * BB * HH + mi];
    float c = 0.0f;                      // cell state in a register for all 512 steps
    float* y = layer ? yext : g_y0;
    float* yrow = y + (size_t)b * (TT * HH) + hid;
    const ulonglong2* wp = reinterpret_cast<const ulonglong2*>(W4 + hid_l * 1024);
    const uint64_t* hrow = hs2 + bl * 258;

    // prefetch xg(t=0)
    size_t xoff = (size_t)b * GG + hid;
    float xi = __ldcs(&g_xg[xoff]);
    float xf = __ldcs(&g_xg[xoff + 256]);
    float xc = __ldcs(&g_xg[xoff + 512]);
    float xo = __ldcs(&g_xg[xoff + 768]);
    __syncthreads();   // W4 staged

    for (int t = 0; t < TT; t++) {
        const int cur = t & 1;
        // stage h(t) slice (8 batches x 256) as duplicated pairs; .cg (L1 stale across SMs)
        {
            const float4* src = reinterpret_cast<const float4*>(g_hbuf[cur] + (size_t)bgrp * 8 * HH);
#pragma unroll
            for (int j = 0; j < 4; j++) {
                int idx = tid + j * 128;          // 0..511
                int r = idx >> 6, k4 = idx & 63;
                float4 v = __ldcg(src + idx);
                uint64_t* d = hs2 + r * 258 + k4 * 4;
                reinterpret_cast<ulonglong2*>(d)[0] = make_ulonglong2(pack2(v.x, v.x), pack2(v.y, v.y));
                reinterpret_cast<ulonglong2*>(d)[1] = make_ulonglong2(pack2(v.z, v.z), pack2(v.w, v.w));
            }
        }
        __syncthreads();

        // gate dot-products: LDS.64 (h,h) + LDS.128 W pair + 2x FFMA2 per k
        uint64_t acc_if = pack2(xi, xf);
        uint64_t acc_go = pack2(xc, xo);
#pragma unroll 8
        for (int k = 0; k < 256; k++) {
            uint64_t hh = hrow[k];
            ulonglong2 wv = wp[k];
            FFMA2(acc_if, wv.x, hh);
            FFMA2(acc_go, wv.y, hh);
        }
        float gi, gf, gc, go;
        unpack2(acc_if, gi, gf);
        unpack2(acc_go, gc, go);

        // prefetch next xg before the barrier (hides DRAM latency behind sync)
        size_t xoff2 = ((size_t)((t + 1 < TT) ? t + 1 : t) * BB + b) * GG + hid;
        xi = __ldcs(&g_xg[xoff2]);
        xf = __ldcs(&g_xg[xoff2 + 256]);
        xc = __ldcs(&g_xg[xoff2 + 512]);
        xo = __ldcs(&g_xg[xoff2 + 768]);

        float i_ = __fdividef(1.0f, 1.0f + __expf(-gi));
        float f_ = __fdividef(1.0f, 1.0f + __expf(-gf));
        float o_ = __fdividef(1.0f, 1.0f + __expf(-go));
        float cn = f_ * c + i_ * tanhf(gc);
        float hn = o_ * tanhf(cn);
        c = cn * mcm;

        yrow[(size_t)t * HH] = hn * mo;
        __stcg(&g_hbuf[cur ^ 1][mi], hn * mh);

        if (t + 1 < TT) {
            __syncthreads();             // all CTA stores precede the release-arrive
            if (tid == 0) {
                red_add_release(&g_bar_arrive, 1u);
                unsigned tgt = (unsigned)(t + 1) * NCTA;
                while (ld_acquire(&g_bar_arrive) < tgt) { }
            }
            __syncthreads();
        }
    }
}

// ---------------- launch (7 graph nodes) ----------------
extern "C" void kernel_launch(void* const* d_in, const int* in_sizes, int n_in,
                              void* d_out, int out_size) {
    const float* x    = (const float*)d_in[0];
    const float* Wih0 = (const float*)d_in[1];
    const float* Whh0 = (const float*)d_in[2];
    const float* bih0 = (const float*)d_in[3];
    const float* bhh0 = (const float*)d_in[4];
    const float* Wih1 = (const float*)d_in[5];
    const float* Whh1 = (const float*)d_in[6];
    const float* bih1 = (const float*)d_in[7];
    const float* bhh1 = (const float*)d_in[8];
    float* out = (float*)d_out;

    const int smem = 16 * 1024 * 4 + 8 * 258 * 8;   // 65536 + 16512 = 82048 B
    cudaFuncSetAttribute(lstm_layer_kernel, cudaFuncAttributeMaxDynamicSharedMemorySize, smem);

    compute_masks_kernel<<<(6 * BB * HH + 255) / 256, 256>>>();

    // layer 0
    zero_state_kernel<<<(BB * HH + 255) / 256, 256>>>();
    gemm_xg_kernel<<<dim3((TT * BB) / 64, GG / 64), 256>>>(x, Wih0, bih0, bhh0, 0);
    lstm_layer_kernel<<<NCTA, 128, smem>>>(Whh0, nullptr, 0);

    // layer 1
    zero_state_kernel<<<(BB * HH + 255) / 256, 256>>>();
    gemm_xg_kernel<<<dim3((TT * BB) / 64, GG / 64), 256>>>(nullptr, Wih1, bih1, bhh1, 1);
    lstm_layer_kernel<<<NCTA, 128, smem>>>(Whh1, out, 1);
}

// round 5
// speedup vs baseline: 3.6585x; 3.6585x over previous
#include <cuda_runtime.h>
#include <cstdint>
#include <cstddef>

#define BB 64      // batch
#define TT 512     // time
#define HH 256     // hidden
#define GG 1024    // 4*H
#define NCTA 128   // 64 hid-groups (4 hids) x 2 batch-groups (32 b)

// ---------------- device scratch (static, no allocations) ----------------
__device__ float g_xg[(size_t)TT * GG * BB];   // [t][g][b] transposed gate pre-activations
__device__ float g_y0[(size_t)BB * TT * HH];   // layer-0 output, [B][T][H]
__device__ float g_hbuf[2][BB * HH];           // ping-pong h carry, [b][hid]
__device__ float g_masks[6 * BB * HH];         // (layer,{out,h,c}) masks [B][H]
__device__ unsigned g_bar_arrive;              // monotone arrival counter (reset per layer)

// ---------------- f32x2 packed math helpers ----------------
__device__ __forceinline__ uint64_t pack2(float lo, float hi) {
    uint64_t r; asm("mov.b64 %0, {%1,%2};" : "=l"(r) : "f"(lo), "f"(hi)); return r;
}
__device__ __forceinline__ void unpack2(uint64_t v, float& lo, float& hi) {
    asm("mov.b64 {%0,%1}, %2;" : "=f"(lo), "=f"(hi) : "l"(v));
}
#define FFMA2(acc, a, b) asm("fma.rn.f32x2 %0, %1, %2, %0;" : "+l"(acc) : "l"(a), "l"(b))

// ---------------- barrier primitives (release/acquire, gpu scope) ----------------
__device__ __forceinline__ void red_add_release(unsigned* p, unsigned v) {
    asm volatile("red.release.gpu.global.add.u32 [%0], %1;" :: "l"(p), "r"(v) : "memory");
}
__device__ __forceinline__ unsigned ld_acquire(const unsigned* p) {
    unsigned v; asm volatile("ld.acquire.gpu.global.u32 %0, [%1];" : "=r"(v) : "l"(p) : "memory");
    return v;
}

// ---------------- Threefry-2x32 (JAX, partitionable) — VALIDATED bit-exact ----------------
__device__ __forceinline__ uint32_t rotl32(uint32_t x, int n) { return __funnelshift_l(x, x, n); }

__device__ __forceinline__ void tf2x32(uint32_t k0, uint32_t k1, uint32_t x0, uint32_t x1,
                                       uint32_t& o0, uint32_t& o1) {
    uint32_t ks2 = k0 ^ k1 ^ 0x1BD11BDAu;
    x0 += k0; x1 += k1;
#define TFR(r) { x0 += x1; x1 = rotl32(x1, (r)); x1 ^= x0; }
    TFR(13) TFR(15) TFR(26) TFR(6)   x0 += k1;  x1 += ks2 + 1u;
    TFR(17) TFR(29) TFR(16) TFR(24)  x0 += ks2; x1 += k0 + 2u;
    TFR(13) TFR(15) TFR(26) TFR(6)   x0 += k0;  x1 += k1 + 3u;
    TFR(17) TFR(29) TFR(16) TFR(24)  x0 += k1;  x1 += ks2 + 4u;
    TFR(13) TFR(15) TFR(26) TFR(6)   x0 += ks2; x1 += k0 + 5u;
#undef TFR
    o0 = x0; o1 = x1;
}

__global__ void compute_masks_kernel() {
    int idx = blockIdx.x * 256 + threadIdx.x;
    if (idx >= 6 * BB * HH) return;
    int l = idx / (3 * BB * HH);
    int j = (idx / (BB * HH)) % 3;
    uint32_t e = (uint32_t)(idx % (BB * HH));
    uint32_t a0, a1, b0, b1, c0, c1;
    tf2x32(0u, 42u, 0u, (uint32_t)l, a0, a1);
    tf2x32(a0, a1, 0u, (uint32_t)j, b0, b1);
    tf2x32(b0, b1, 0u, e, c0, c1);
    uint32_t bits = c0 ^ c1;
    float u = __uint_as_float((bits >> 9) | 0x3f800000u) - 1.0f;
    g_masks[idx] = (u < 0.75f) ? (1.0f / 0.75f) : 0.0f;
}

__global__ void zero_state_kernel() {
    int i = blockIdx.x * 256 + threadIdx.x;
    if (i < BB * HH) {
        g_hbuf[0][i] = 0.0f;
        g_hbuf[1][i] = 0.0f;
    }
    if (i == 0) g_bar_arrive = 0u;   // reset per layer / per replay (determinism)
}

// ---------------- big GEMM (f32x2): xg[t][g][b] = sum_k A[b][t][k]*W[g][k] + bih+bhh ----------------
// m = t*64 + b. A: [B][T][256]; W: [1024][256]. 64x64 tile, 256 threads, 4x4 per thread.
__global__ void gemm_xg_kernel(const float* __restrict__ Aext, const float* __restrict__ W,
                               const float* __restrict__ bih, const float* __restrict__ bhh,
                               int use_y0) {
    const float* A = use_y0 ? g_y0 : Aext;
    __shared__ uint64_t As2[16][65];   // (a,a) pairs
    __shared__ float Bs[16][68];
    int tid = threadIdx.x;
    int lr = tid >> 2;            // 0..63
    int lc = (tid & 3) << 2;      // 0,4,8,12
    int m = blockIdx.x * 64 + lr;
    const float* Arow = A + ((size_t)(m & 63) * TT + (size_t)(m >> 6)) * HH;
    const float* Wrow = W + (size_t)(blockIdx.y * 64 + lr) * 256;
    int tx = tid & 15, ty = tid >> 4;
    uint64_t accp[4][2];
#pragma unroll
    for (int i = 0; i < 4; i++) { accp[i][0] = 0ull; accp[i][1] = 0ull; }
    for (int k0 = 0; k0 < 256; k0 += 16) {
        float4 av = *reinterpret_cast<const float4*>(Arow + k0 + lc);
        float4 wv = *reinterpret_cast<const float4*>(Wrow + k0 + lc);
        As2[lc + 0][lr] = pack2(av.x, av.x);
        As2[lc + 1][lr] = pack2(av.y, av.y);
        As2[lc + 2][lr] = pack2(av.z, av.z);
        As2[lc + 3][lr] = pack2(av.w, av.w);
        Bs[lc + 0][lr] = wv.x; Bs[lc + 1][lr] = wv.y; Bs[lc + 2][lr] = wv.z; Bs[lc + 3][lr] = wv.w;
        __syncthreads();
#pragma unroll
        for (int kk = 0; kk < 16; kk++) {
            ulonglong2 w2 = *reinterpret_cast<const ulonglong2*>(&Bs[kk][tx << 2]);
#pragma unroll
            for (int i = 0; i < 4; i++) {
                uint64_t aa = As2[kk][(ty << 2) + i];
                FFMA2(accp[i][0], w2.x, aa);
                FFMA2(accp[i][1], w2.y, aa);
            }
        }
        __syncthreads();
    }
    int n0 = blockIdx.y * 64 + (tx << 2);
    float bv0 = bih[n0 + 0] + bhh[n0 + 0];
    float bv1 = bih[n0 + 1] + bhh[n0 + 1];
    float bv2 = bih[n0 + 2] + bhh[n0 + 2];
    float bv3 = bih[n0 + 3] + bhh[n0 + 3];
#pragma unroll
    for (int i = 0; i < 4; i++) {
        int m2 = blockIdx.x * 64 + (ty << 2) + i;
        size_t tt = (size_t)(m2 >> 6), bb = (size_t)(m2 & 63);
        float a0, a1, a2, a3;
        unpack2(accp[i][0], a0, a1);
        unpack2(accp[i][1], a2, a3);
        size_t base = (tt * GG + (size_t)n0) * BB + bb;
        g_xg[base + 0 * BB] = a0 + bv0;
        g_xg[base + 1 * BB] = a1 + bv1;
        g_xg[base + 2 * BB] = a2 + bv2;
        g_xg[base + 3 * BB] = a3 + bv3;
    }
}

// ---------------- persistent per-layer recurrence kernel ----------------
// 128 CTAs x 128 threads. CTA = (hgrp: 4 hids, bgrp: 32 batches).
// tid: hid_l = tid&3, b_l = tid>>2. Warp = 8 b x 4 hid.
// smem: W4 [4 hid][4 gate][256 k], hid stride 1032 (bank-staggered). hs [32 b][k], stride 260.
#define WSTR 1032
__global__ void __launch_bounds__(128, 1) lstm_layer_kernel(const float* __restrict__ Whh,
                                                            float* __restrict__ yext, int layer) {
    extern __shared__ float sm[];
    float* W4 = sm;                 // 4*1032 = 4128 floats
    float* hs = sm + 4 * WSTR;      // 32*260 = 8320 floats
    const int tid = threadIdx.x;
    const int hid_l = tid & 3;
    const int b_l = tid >> 2;       // 0..31
    const int hgrp = blockIdx.x >> 1;
    const int bgrp = blockIdx.x & 1;
    const int hid = hgrp * 4 + hid_l;
    const int b = bgrp * 32 + b_l;

    // stage W_hh once: W4[hid'][gate][k] (gate rows i,f,g,o at 0,256,512,768 of Whh)
    for (int j = 0; j < 8; j++) {
        int f = tid + j * 128;              // float4 index, 0..1023
        int hidp = f >> 8, gate = (f >> 6) & 3, k4 = f & 63;
        float4 v = __ldg(reinterpret_cast<const float4*>(
            Whh + ((size_t)(gate << 8) + (size_t)(hgrp * 4 + hidp)) * 256) + k4);
        *reinterpret_cast<float4*>(W4 + hidp * WSTR + gate * 256 + k4 * 4) = v;
    }

    const int mi = b * HH + hid;
    const float mo  = g_masks[(layer * 3 + 0) * BB * HH + mi];
    const float mh  = g_masks[(layer * 3 + 1) * BB * HH + mi];
    const float mcm = g_masks[(layer * 3 + 2) * BB * HH + mi];
    float c = 0.0f;                 // cell state in a register for all 512 steps
    float* y = layer ? yext : g_y0;
    float* yrow = y + (size_t)b * (TT * HH) + hid;
    const float* wbase = W4 + hid_l * WSTR;
    const float* hrow = hs + b_l * 260;

    // prefetch xg(t=0): transposed layout [t][g][b]
    {
        size_t x0 = (size_t)hid * BB + b;
        // done below in loop variables
    }
    float xi, xf, xc, xo;
    {
        size_t xb = (size_t)hid * BB + b;
        xi = __ldcs(&g_xg[xb]);
        xf = __ldcs(&g_xg[xb + (size_t)256 * BB]);
        xc = __ldcs(&g_xg[xb + (size_t)512 * BB]);
        xo = __ldcs(&g_xg[xb + (size_t)768 * BB]);
    }
    __syncthreads();   // W4 staged

    for (int t = 0; t < TT; t++) {
        const int cur = t & 1;
        // stage h(t) slice [32 b][256 k] from g_hbuf[cur][b][hid']; coalesced LDG.128 + STS.128
        {
            const float4* src = reinterpret_cast<const float4*>(g_hbuf[cur] + (size_t)bgrp * 32 * HH);
#pragma unroll
            for (int j = 0; j < 16; j++) {
                int idx = tid + j * 128;          // 0..2047 float4s
                int r = idx >> 6, k4 = idx & 63;
                float4 v = __ldcg(src + idx);
                *reinterpret_cast<float4*>(hs + r * 260 + k4 * 4) = v;
            }
        }
        __syncthreads();

        // gate dot-products: f32x2 accumulators paired over k
        uint64_t a_i = pack2(xi, 0.0f);
        uint64_t a_f = pack2(xf, 0.0f);
        uint64_t a_c = pack2(xc, 0.0f);
        uint64_t a_o = pack2(xo, 0.0f);
#pragma unroll 8
        for (int k = 0; k < 256; k += 4) {
            ulonglong2 h01 = *reinterpret_cast<const ulonglong2*>(hrow + k);
            ulonglong2 wi = *reinterpret_cast<const ulonglong2*>(wbase + k);
            ulonglong2 wf = *reinterpret_cast<const ulonglong2*>(wbase + 256 + k);
            ulonglong2 wc = *reinterpret_cast<const ulonglong2*>(wbase + 512 + k);
            ulonglong2 wo = *reinterpret_cast<const ulonglong2*>(wbase + 768 + k);
            FFMA2(a_i, wi.x, h01.x); FFMA2(a_i, wi.y, h01.y);
            FFMA2(a_f, wf.x, h01.x); FFMA2(a_f, wf.y, h01.y);
            FFMA2(a_c, wc.x, h01.x); FFMA2(a_c, wc.y, h01.y);
            FFMA2(a_o, wo.x, h01.x); FFMA2(a_o, wo.y, h01.y);
        }
        float gi, gf, gc, go, tmp;
        unpack2(a_i, gi, tmp); gi += tmp;
        unpack2(a_f, gf, tmp); gf += tmp;
        unpack2(a_c, gc, tmp); gc += tmp;
        unpack2(a_o, go, tmp); go += tmp;

        // prefetch next xg before the barrier (hides DRAM latency behind sync)
        {
            int tn = (t + 1 < TT) ? t + 1 : t;
            size_t xb = ((size_t)tn * GG + (size_t)hid) * BB + b;
            xi = __ldcs(&g_xg[xb]);
            xf = __ldcs(&g_xg[xb + (size_t)256 * BB]);
            xc = __ldcs(&g_xg[xb + (size_t)512 * BB]);
            xo = __ldcs(&g_xg[xb + (size_t)768 * BB]);
        }

        float i_ = __fdividef(1.0f, 1.0f + __expf(-gi));
        float f_ = __fdividef(1.0f, 1.0f + __expf(-gf));
        float o_ = __fdividef(1.0f, 1.0f + __expf(-go));
        float cn = f_ * c + i_ * tanhf(gc);
        float hn = o_ * tanhf(cn);
        c = cn * mcm;

        yrow[(size_t)t * HH] = hn * mo;
        __stcg(&g_hbuf[cur ^ 1][mi], hn * mh);

        if (t + 1 < TT) {
            __syncthreads();             // all CTA stores precede the release-arrive
            if (tid == 0) {
                red_add_release(&g_bar_arrive, 1u);
                unsigned tgt = (unsigned)(t + 1) * NCTA;
                while (ld_acquire(&g_bar_arrive) < tgt) { }
            }
            __syncthreads();
        }
    }
}

// ---------------- launch (7 graph nodes) ----------------
extern "C" void kernel_launch(void* const* d_in, const int* in_sizes, int n_in,
                              void* d_out, int out_size) {
    const float* x    = (const float*)d_in[0];
    const float* Wih0 = (const float*)d_in[1];
    const float* Whh0 = (const float*)d_in[2];
    const float* bih0 = (const float*)d_in[3];
    const float* bhh0 = (const float*)d_in[4];
    const float* Wih1 = (const float*)d_in[5];
    const float* Whh1 = (const float*)d_in[6];
    const float* bih1 = (const float*)d_in[7];
    const float* bhh1 = (const float*)d_in[8];
    float* out = (float*)d_out;

    const int smem = (4 * WSTR + 32 * 260) * 4;   // (4128 + 8320)*4 = 49792 B
    cudaFuncSetAttribute(lstm_layer_kernel, cudaFuncAttributeMaxDynamicSharedMemorySize, smem);

    compute_masks_kernel<<<(6 * BB * HH + 255) / 256, 256>>>();

    // layer 0
    zero_state_kernel<<<(BB * HH + 255) / 256, 256>>>();
    gemm_xg_kernel<<<dim3((TT * BB) / 64, GG / 64), 256>>>(x, Wih0, bih0, bhh0, 0);
    lstm_layer_kernel<<<NCTA, 128, smem>>>(Whh0, nullptr, 0);

    // layer 1
    zero_state_kernel<<<(BB * HH + 255) / 256, 256>>>();
    gemm_xg_kernel<<<dim3((TT * BB) / 64, GG / 64), 256>>>(nullptr, Wih1, bih1, bhh1, 1);
    lstm_layer_kernel<<<NCTA, 128, smem>>>(Whh1, out, 1);
}

// round 6
// speedup vs baseline: 3.9123x; 1.0694x over previous
#include <cuda_runtime.h>
#include <cstdint>
#include <cstddef>

#define BB 64      // batch
#define TT 512     // time
#define HH 256     // hidden
#define GG 1024    // 4*H
#define NCTA 128   // 32 hid-groups (8 hids) x 4 batch-groups (16 b)
#define WSTR 1028  // W smem hid stride: 1028 mod 32 banks = 4 -> 8 distinct 16B phases

// ---------------- device scratch (static, no allocations) ----------------
__device__ float g_xg[(size_t)TT * BB * GG];   // [t*64+b][4H] row-major gate pre-activations
__device__ float g_y0[(size_t)BB * TT * HH];   // layer-0 output, [B][T][H]
__device__ float g_hbuf[2][BB * HH];           // ping-pong h carry, [b][hid]
__device__ float g_masks[6 * BB * HH];         // (layer,{out,h,c}) masks [B][H]
__device__ unsigned g_bar_arrive;              // monotone arrival counter (reset per layer)

// ---------------- f32x2 packed math helpers ----------------
__device__ __forceinline__ uint64_t pack2(float lo, float hi) {
    uint64_t r; asm("mov.b64 %0, {%1,%2};" : "=l"(r) : "f"(lo), "f"(hi)); return r;
}
__device__ __forceinline__ void unpack2(uint64_t v, float& lo, float& hi) {
    asm("mov.b64 {%0,%1}, %2;" : "=f"(lo), "=f"(hi) : "l"(v));
}
#define FFMA2(acc, a, b) asm("fma.rn.f32x2 %0, %1, %2, %0;" : "+l"(acc) : "l"(a), "l"(b))

// ---------------- barrier primitives (release/acquire, gpu scope) ----------------
__device__ __forceinline__ void red_add_release(unsigned* p, unsigned v) {
    asm volatile("red.release.gpu.global.add.u32 [%0], %1;" :: "l"(p), "r"(v) : "memory");
}
__device__ __forceinline__ unsigned ld_acquire(const unsigned* p) {
    unsigned v; asm volatile("ld.acquire.gpu.global.u32 %0, [%1];" : "=r"(v) : "l"(p) : "memory");
    return v;
}

// ---------------- Threefry-2x32 (JAX, partitionable) — VALIDATED bit-exact ----------------
__device__ __forceinline__ uint32_t rotl32(uint32_t x, int n) { return __funnelshift_l(x, x, n); }

__device__ __forceinline__ void tf2x32(uint32_t k0, uint32_t k1, uint32_t x0, uint32_t x1,
                                       uint32_t& o0, uint32_t& o1) {
    uint32_t ks2 = k0 ^ k1 ^ 0x1BD11BDAu;
    x0 += k0; x1 += k1;
#define TFR(r) { x0 += x1; x1 = rotl32(x1, (r)); x1 ^= x0; }
    TFR(13) TFR(15) TFR(26) TFR(6)   x0 += k1;  x1 += ks2 + 1u;
    TFR(17) TFR(29) TFR(16) TFR(24)  x0 += ks2; x1 += k0 + 2u;
    TFR(13) TFR(15) TFR(26) TFR(6)   x0 += k0;  x1 += k1 + 3u;
    TFR(17) TFR(29) TFR(16) TFR(24)  x0 += k1;  x1 += ks2 + 4u;
    TFR(13) TFR(15) TFR(26) TFR(6)   x0 += ks2; x1 += k0 + 5u;
#undef TFR
    o0 = x0; o1 = x1;
}

__global__ void compute_masks_kernel() {
    int idx = blockIdx.x * 256 + threadIdx.x;
    if (idx >= 6 * BB * HH) return;
    int l = idx / (3 * BB * HH);
    int j = (idx / (BB * HH)) % 3;
    uint32_t e = (uint32_t)(idx % (BB * HH));
    uint32_t a0, a1, b0, b1, c0, c1;
    tf2x32(0u, 42u, 0u, (uint32_t)l, a0, a1);
    tf2x32(a0, a1, 0u, (uint32_t)j, b0, b1);
    tf2x32(b0, b1, 0u, e, c0, c1);
    uint32_t bits = c0 ^ c1;
    float u = __uint_as_float((bits >> 9) | 0x3f800000u) - 1.0f;
    g_masks[idx] = (u < 0.75f) ? (1.0f / 0.75f) : 0.0f;
}

__global__ void zero_state_kernel() {
    int i = blockIdx.x * 256 + threadIdx.x;
    if (i < BB * HH) {
        g_hbuf[0][i] = 0.0f;
        g_hbuf[1][i] = 0.0f;
    }
    if (i == 0) g_bar_arrive = 0u;   // reset per layer / per replay (determinism)
}

// ---------------- big GEMM (f32x2, double-buffered): xg[m][g] = A[b][t][:].W[g][:] + bias ----------------
// m = t*64 + b. A: [B][T][256]; W: [1024][256]. 128x64 tile, 256 threads, 8x4 per thread.
__global__ void __launch_bounds__(256) gemm_xg_kernel(const float* __restrict__ Aext,
                                                      const float* __restrict__ W,
                                                      const float* __restrict__ bih,
                                                      const float* __restrict__ bhh,
                                                      int use_y0) {
    const float* A = use_y0 ? g_y0 : Aext;
    __shared__ uint64_t As2[16][132];   // (a,a) pairs, [k][m], pad to avoid phase repeat
    __shared__ float Bs[16][68];        // [k][n]
    const int tid = threadIdx.x;
    const int arow_l = tid >> 1;          // 0..127
    const int ak = (tid & 1) << 3;        // 0 or 8
    const int m = blockIdx.x * 128 + arow_l;
    const float* Arow = A + ((size_t)(m & 63) * TT + (size_t)(m >> 6)) * HH;
    const int brow_l = tid >> 2;          // 0..63
    const int bk = (tid & 3) << 2;        // 0,4,8,12
    const float* Wrow = W + (size_t)(blockIdx.y * 64 + brow_l) * HH;
    const int tx = tid & 15, ty = tid >> 4;

    uint64_t acc[8][2];
#pragma unroll
    for (int i = 0; i < 8; i++) { acc[i][0] = 0ull; acc[i][1] = 0ull; }

    // register prefetch of first k-tile
    float4 a0v = *reinterpret_cast<const float4*>(Arow + ak);
    float4 a1v = *reinterpret_cast<const float4*>(Arow + ak + 4);
    float4 bv  = *reinterpret_cast<const float4*>(Wrow + bk);

    for (int k0 = 0; k0 < 256; k0 += 16) {
        As2[ak + 0][arow_l] = pack2(a0v.x, a0v.x);
        As2[ak + 1][arow_l] = pack2(a0v.y, a0v.y);
        As2[ak + 2][arow_l] = pack2(a0v.z, a0v.z);
        As2[ak + 3][arow_l] = pack2(a0v.w, a0v.w);
        As2[ak + 4][arow_l] = pack2(a1v.x, a1v.x);
        As2[ak + 5][arow_l] = pack2(a1v.y, a1v.y);
        As2[ak + 6][arow_l] = pack2(a1v.z, a1v.z);
        As2[ak + 7][arow_l] = pack2(a1v.w, a1v.w);
        Bs[bk + 0][brow_l] = bv.x;
        Bs[bk + 1][brow_l] = bv.y;
        Bs[bk + 2][brow_l] = bv.z;
        Bs[bk + 3][brow_l] = bv.w;
        __syncthreads();
        if (k0 + 16 < 256) {   // overlap next tile's LDGs with this tile's FFMA2 burst
            a0v = *reinterpret_cast<const float4*>(Arow + k0 + 16 + ak);
            a1v = *reinterpret_cast<const float4*>(Arow + k0 + 16 + ak + 4);
            bv  = *reinterpret_cast<const float4*>(Wrow + k0 + 16 + bk);
        }
#pragma unroll
        for (int kk = 0; kk < 16; kk++) {
            ulonglong2 w2 = *reinterpret_cast<const ulonglong2*>(&Bs[kk][tx << 2]);
#pragma unroll
            for (int i = 0; i < 8; i++) {
                uint64_t aa = As2[kk][(ty << 3) + i];
                FFMA2(acc[i][0], w2.x, aa);
                FFMA2(acc[i][1], w2.y, aa);
            }
        }
        __syncthreads();
    }
    const int n0 = blockIdx.y * 64 + (tx << 2);
    const float bv0 = bih[n0 + 0] + bhh[n0 + 0];
    const float bv1 = bih[n0 + 1] + bhh[n0 + 1];
    const float bv2 = bih[n0 + 2] + bhh[n0 + 2];
    const float bv3 = bih[n0 + 3] + bhh[n0 + 3];
#pragma unroll
    for (int i = 0; i < 8; i++) {
        int m2 = blockIdx.x * 128 + (ty << 3) + i;
        float a0, a1, a2, a3;
        unpack2(acc[i][0], a0, a1);
        unpack2(acc[i][1], a2, a3);
        *reinterpret_cast<float4*>(&g_xg[(size_t)m2 * GG + n0]) =
            make_float4(a0 + bv0, a1 + bv1, a2 + bv2, a3 + bv3);
    }
}

// ---------------- persistent per-layer recurrence kernel ----------------
// 128 CTAs x 128 threads (1/SM). CTA = (hgrp: 8 hids, bgrp: 16 batches).
// tid: hid_l = tid&7, b_l = tid>>3. Warp = 4 b x 8 hid.
__global__ void __launch_bounds__(128, 1) lstm_layer_kernel(const float* __restrict__ Whh,
                                                            float* __restrict__ yext, int layer) {
    extern __shared__ float sm[];
    float* W4 = sm;                  // [8 hid][WSTR] (gate-major within: [gate*256 + k])
    float* hs = sm + 8 * WSTR;       // [16 b][260]
    const int tid = threadIdx.x;
    const int hid_l = tid & 7;
    const int b_l = tid >> 3;            // 0..15
    const int hgrp = blockIdx.x >> 2;    // 0..31
    const int bgrp = blockIdx.x & 3;     // 0..3
    const int hid = hgrp * 8 + hid_l;
    const int b = bgrp * 16 + b_l;

    // stage W_hh once: W4[hidp][gate*256 + k], gates i,f,g,o
#pragma unroll
    for (int j = 0; j < 16; j++) {
        int f = tid + (j << 7);              // float4 index 0..2047
        int hidp = f >> 8, gate = (f >> 6) & 3, k4 = f & 63;
        float4 v = __ldg(reinterpret_cast<const float4*>(
            Whh + ((size_t)(gate << 8) + (size_t)(hgrp * 8 + hidp)) * HH) + k4);
        *reinterpret_cast<float4*>(W4 + hidp * WSTR + gate * 256 + (k4 << 2)) = v;
    }

    const int mi = b * HH + hid;
    const float mo  = g_masks[(layer * 3 + 0) * BB * HH + mi];
    const float mh  = g_masks[(layer * 3 + 1) * BB * HH + mi];
    const float mcm = g_masks[(layer * 3 + 2) * BB * HH + mi];
    float c = 0.0f;                        // cell state in a register for all 512 steps
    float* y = layer ? yext : g_y0;
    float* yrow = y + (size_t)b * (TT * HH) + hid;
    const float* wbase = W4 + hid_l * WSTR;
    const float* hrow = hs + b_l * 260;

    // prefetch xg(t=0), row-major [t*64+b][4H]
    float xi, xf, xc, xo;
    {
        size_t xb = (size_t)b * GG + hid;
        xi = __ldcs(&g_xg[xb]);
        xf = __ldcs(&g_xg[xb + 256]);
        xc = __ldcs(&g_xg[xb + 512]);
        xo = __ldcs(&g_xg[xb + 768]);
    }
    __syncthreads();   // W4 staged

    for (int t = 0; t < TT; t++) {
        const int cur = t & 1;
        // stage h(t) slice [16 b][256 k]; coalesced LDG.128(.cg) + conflict-free STS.128
        {
            const float4* src = reinterpret_cast<const float4*>(g_hbuf[cur] + (size_t)bgrp * 16 * HH);
#pragma unroll
            for (int j = 0; j < 8; j++) {
                int idx = tid + (j << 7);          // 0..1023 float4s
                float4 v = __ldcg(src + idx);
                int r = idx >> 6, k4 = idx & 63;
                *reinterpret_cast<float4*>(hs + r * 260 + (k4 << 2)) = v;
            }
        }
        __syncthreads();

        // gate dot-products: f32x2 accumulators paired over k
        uint64_t a_i = pack2(xi, 0.0f);
        uint64_t a_f = pack2(xf, 0.0f);
        uint64_t a_c = pack2(xc, 0.0f);
        uint64_t a_o = pack2(xo, 0.0f);
#pragma unroll 8
        for (int k = 0; k < 256; k += 4) {
            ulonglong2 h01 = *reinterpret_cast<const ulonglong2*>(hrow + k);
            ulonglong2 wi = *reinterpret_cast<const ulonglong2*>(wbase + k);
            ulonglong2 wf = *reinterpret_cast<const ulonglong2*>(wbase + 256 + k);
            ulonglong2 wc = *reinterpret_cast<const ulonglong2*>(wbase + 512 + k);
            ulonglong2 wo = *reinterpret_cast<const ulonglong2*>(wbase + 768 + k);
            FFMA2(a_i, wi.x, h01.x); FFMA2(a_i, wi.y, h01.y);
            FFMA2(a_f, wf.x, h01.x); FFMA2(a_f, wf.y, h01.y);
            FFMA2(a_c, wc.x, h01.x); FFMA2(a_c, wc.y, h01.y);
            FFMA2(a_o, wo.x, h01.x); FFMA2(a_o, wo.y, h01.y);
        }
        float gi, gf, gc, go, tmp;
        unpack2(a_i, gi, tmp); gi += tmp;
        unpack2(a_f, gf, tmp); gf += tmp;
        unpack2(a_c, gc, tmp); gc += tmp;
        unpack2(a_o, go, tmp); go += tmp;

        // prefetch next xg before the barrier (hides DRAM latency behind sync)
        {
            int tn = (t + 1 < TT) ? t + 1 : t;
            size_t xb = ((size_t)tn * BB + b) * GG + hid;
            xi = __ldcs(&g_xg[xb]);
            xf = __ldcs(&g_xg[xb + 256]);
            xc = __ldcs(&g_xg[xb + 512]);
            xo = __ldcs(&g_xg[xb + 768]);
        }

        float i_ = __fdividef(1.0f, 1.0f + __expf(-gi));
        float f_ = __fdividef(1.0f, 1.0f + __expf(-gf));
        float o_ = __fdividef(1.0f, 1.0f + __expf(-go));
        float tg = 1.0f - __fdividef(2.0f, __expf(2.0f * gc) + 1.0f);   // tanh(gc)
        float cn = f_ * c + i_ * tg;
        float th = 1.0f - __fdividef(2.0f, __expf(2.0f * cn) + 1.0f);   // tanh(cn)
        float hn = o_ * th;
        c = cn * mcm;

        yrow[(size_t)t * HH] = hn * mo;
        __stcg(&g_hbuf[cur ^ 1][mi], hn * mh);

        if (t + 1 < TT) {
            __syncthreads();             // all CTA stores precede the release-arrive
            if (tid == 0) {
                red_add_release(&g_bar_arrive, 1u);
                unsigned tgt = (unsigned)(t + 1) * NCTA;
                while (ld_acquire(&g_bar_arrive) < tgt) { }
            }
            __syncthreads();
        }
    }
}

// ---------------- launch (7 graph nodes) ----------------
extern "C" void kernel_launch(void* const* d_in, const int* in_sizes, int n_in,
                              void* d_out, int out_size) {
    const float* x    = (const float*)d_in[0];
    const float* Wih0 = (const float*)d_in[1];
    const float* Whh0 = (const float*)d_in[2];
    const float* bih0 = (const float*)d_in[3];
    const float* bhh0 = (const float*)d_in[4];
    const float* Wih1 = (const float*)d_in[5];
    const float* Whh1 = (const float*)d_in[6];
    const float* bih1 = (const float*)d_in[7];
    const float* bhh1 = (const float*)d_in[8];
    float* out = (float*)d_out;

    const int smem = (8 * WSTR + 16 * 260) * 4;   // (8224 + 4160)*4 = 49536 B
    cudaFuncSetAttribute(lstm_layer_kernel, cudaFuncAttributeMaxDynamicSharedMemorySize, smem);

    compute_masks_kernel<<<(6 * BB * HH + 255) / 256, 256>>>();

    // layer 0
    zero_state_kernel<<<(BB * HH + 255) / 256, 256>>>();
    gemm_xg_kernel<<<dim3((TT * BB) / 128, GG / 64), 256>>>(x, Wih0, bih0, bhh0, 0);
    lstm_layer_kernel<<<NCTA, 128, smem>>>(Whh0, nullptr, 0);

    // layer 1
    zero_state_kernel<<<(BB * HH + 255) / 256, 256>>>();
    gemm_xg_kernel<<<dim3((TT * BB) / 128, GG / 64), 256>>>(nullptr, Wih1, bih1, bhh1, 1);
    lstm_layer_kernel<<<NCTA, 128, smem>>>(Whh1, out, 1);
}

// round 9
// speedup vs baseline: 4.5319x; 1.1583x over previous
#include <cuda_runtime.h>
#include <cstdint>
#include <cstddef>

#define BB 64      // batch
#define TT 512     // time
#define HH 256     // hidden
#define GG 1024    // 4*H
#define NCTA 128   // 32 hid-groups (8 hids) x 4 batch-groups (16 b)
#define WSTR 1028  // W smem hid stride (floats): 4112B mod 128B = 16 -> staggered phases

// ---------------- device scratch (static, no allocations) ----------------
__device__ float g_xg[(size_t)TT * BB * GG];   // [t*64+b][4H] row-major gate pre-activations
__device__ float g_y0[(size_t)BB * TT * HH];   // layer-0 output, [B][T][H]
__device__ float g_hbuf[2][BB * HH];           // ping-pong h carry, [b][hid]
__device__ float g_masks[6 * BB * HH];         // (layer,{out,h,c}) masks [B][H]
__device__ unsigned g_bar_arrive;              // monotone arrival counter (reset per layer)

// ---------------- f32x2 packed math helpers ----------------
__device__ __forceinline__ uint64_t pack2(float lo, float hi) {
    uint64_t r; asm("mov.b64 %0, {%1,%2};" : "=l"(r) : "f"(lo), "f"(hi)); return r;
}
__device__ __forceinline__ void unpack2(uint64_t v, float& lo, float& hi) {
    asm("mov.b64 {%0,%1}, %2;" : "=f"(lo), "=f"(hi) : "l"(v));
}
#define FFMA2(acc, a, b) asm("fma.rn.f32x2 %0, %1, %2, %0;" : "+l"(acc) : "l"(a), "l"(b))

// ---------------- barrier primitives (release/acquire, gpu scope) ----------------
__device__ __forceinline__ void red_add_release(unsigned* p, unsigned v) {
    asm volatile("red.release.gpu.global.add.u32 [%0], %1;" :: "l"(p), "r"(v) : "memory");
}
__device__ __forceinline__ unsigned ld_acquire(const unsigned* p) {
    unsigned v; asm volatile("ld.acquire.gpu.global.u32 %0, [%1];" : "=r"(v) : "l"(p) : "memory");
    return v;
}

// ---------------- Threefry-2x32 (JAX, partitionable) — VALIDATED bit-exact ----------------
__device__ __forceinline__ uint32_t rotl32(uint32_t x, int n) { return __funnelshift_l(x, x, n); }

__device__ __forceinline__ void tf2x32(uint32_t k0, uint32_t k1, uint32_t x0, uint32_t x1,
                                       uint32_t& o0, uint32_t& o1) {
    uint32_t ks2 = k0 ^ k1 ^ 0x1BD11BDAu;
    x0 += k0; x1 += k1;
#define TFR(r) { x0 += x1; x1 = rotl32(x1, (r)); x1 ^= x0; }
    TFR(13) TFR(15) TFR(26) TFR(6)   x0 += k1;  x1 += ks2 + 1u;
    TFR(17) TFR(29) TFR(16) TFR(24)  x0 += ks2; x1 += k0 + 2u;
    TFR(13) TFR(15) TFR(26) TFR(6)   x0 += k0;  x1 += k1 + 3u;
    TFR(17) TFR(29) TFR(16) TFR(24)  x0 += k1;  x1 += ks2 + 4u;
    TFR(13) TFR(15) TFR(26) TFR(6)   x0 += ks2; x1 += k0 + 5u;
#undef TFR
    o0 = x0; o1 = x1;
}

__global__ void compute_masks_kernel() {
    int idx = blockIdx.x * 256 + threadIdx.x;
    if (idx >= 6 * BB * HH) return;
    int l = idx / (3 * BB * HH);
    int j = (idx / (BB * HH)) % 3;
    uint32_t e = (uint32_t)(idx % (BB * HH));
    uint32_t a0, a1, b0, b1, c0, c1;
    tf2x32(0u, 42u, 0u, (uint32_t)l, a0, a1);
    tf2x32(a0, a1, 0u, (uint32_t)j, b0, b1);
    tf2x32(b0, b1, 0u, e, c0, c1);
    uint32_t bits = c0 ^ c1;
    float u = __uint_as_float((bits >> 9) | 0x3f800000u) - 1.0f;
    g_masks[idx] = (u < 0.75f) ? (1.0f / 0.75f) : 0.0f;
}

__global__ void zero_state_kernel() {
    int i = blockIdx.x * 256 + threadIdx.x;
    if (i < BB * HH) {
        g_hbuf[0][i] = 0.0f;
        g_hbuf[1][i] = 0.0f;
    }
    if (i == 0) g_bar_arrive = 0u;   // reset per layer / per replay (determinism)
}

// ---------------- big GEMM (f32x2, double-buffered, LDS.128 A-feed) ----------------
// m = t*64 + b. A: [B][T][256]; W: [1024][256]. 128x64 tile, 256 threads, 8x4 per thread.
__global__ void __launch_bounds__(256) gemm_xg_kernel(const float* __restrict__ Aext,
                                                      const float* __restrict__ W,
                                                      const float* __restrict__ bih,
                                                      const float* __restrict__ bhh,
                                                      int use_y0) {
    const float* A = use_y0 ? g_y0 : Aext;
    __shared__ uint64_t As2[16][132];   // (a,a) dup pairs, [k][m]
    __shared__ float Bs[16][68];        // [k][n]
    const int tid = threadIdx.x;
    const int arow_l = tid >> 1;
    const int ak = (tid & 1) << 3;
    const int m = blockIdx.x * 128 + arow_l;
    const float* Arow = A + ((size_t)(m & 63) * TT + (size_t)(m >> 6)) * HH;
    const int brow_l = tid >> 2;
    const int bk = (tid & 3) << 2;
    const float* Wrow = W + (size_t)(blockIdx.y * 64 + brow_l) * HH;
    const int tx = tid & 15, ty = tid >> 4;

    uint64_t acc[8][2];
#pragma unroll
    for (int i = 0; i < 8; i++) { acc[i][0] = 0ull; acc[i][1] = 0ull; }

    float4 a0v = *reinterpret_cast<const float4*>(Arow + ak);
    float4 a1v = *reinterpret_cast<const float4*>(Arow + ak + 4);
    float4 bv  = *reinterpret_cast<const float4*>(Wrow + bk);

    for (int k0 = 0; k0 < 256; k0 += 16) {
        As2[ak + 0][arow_l] = pack2(a0v.x, a0v.x);
        As2[ak + 1][arow_l] = pack2(a0v.y, a0v.y);
        As2[ak + 2][arow_l] = pack2(a0v.z, a0v.z);
        As2[ak + 3][arow_l] = pack2(a0v.w, a0v.w);
        As2[ak + 4][arow_l] = pack2(a1v.x, a1v.x);
        As2[ak + 5][arow_l] = pack2(a1v.y, a1v.y);
        As2[ak + 6][arow_l] = pack2(a1v.z, a1v.z);
        As2[ak + 7][arow_l] = pack2(a1v.w, a1v.w);
        Bs[bk + 0][brow_l] = bv.x;
        Bs[bk + 1][brow_l] = bv.y;
        Bs[bk + 2][brow_l] = bv.z;
        Bs[bk + 3][brow_l] = bv.w;
        __syncthreads();
        if (k0 + 16 < 256) {   // overlap next tile's LDGs with this tile's FFMA2 burst
            a0v = *reinterpret_cast<const float4*>(Arow + k0 + 16 + ak);
            a1v = *reinterpret_cast<const float4*>(Arow + k0 + 16 + ak + 4);
            bv  = *reinterpret_cast<const float4*>(Wrow + k0 + 16 + bk);
        }
#pragma unroll
        for (int kk = 0; kk < 16; kk++) {
            ulonglong2 w2 = *reinterpret_cast<const ulonglong2*>(&Bs[kk][tx << 2]);
            const ulonglong2* ap = reinterpret_cast<const ulonglong2*>(&As2[kk][ty << 3]);
            ulonglong2 a01 = ap[0];   // LDS.128: dup-pairs for rows i=0,1
            ulonglong2 a23 = ap[1];
            ulonglong2 a45 = ap[2];
            ulonglong2 a67 = ap[3];
            FFMA2(acc[0][0], w2.x, a01.x); FFMA2(acc[0][1], w2.y, a01.x);
            FFMA2(acc[1][0], w2.x, a01.y); FFMA2(acc[1][1], w2.y, a01.y);
            FFMA2(acc[2][0], w2.x, a23.x); FFMA2(acc[2][1], w2.y, a23.x);
            FFMA2(acc[3][0], w2.x, a23.y); FFMA2(acc[3][1], w2.y, a23.y);
            FFMA2(acc[4][0], w2.x, a45.x); FFMA2(acc[4][1], w2.y, a45.x);
            FFMA2(acc[5][0], w2.x, a45.y); FFMA2(acc[5][1], w2.y, a45.y);
            FFMA2(acc[6][0], w2.x, a67.x); FFMA2(acc[6][1], w2.y, a67.x);
            FFMA2(acc[7][0], w2.x, a67.y); FFMA2(acc[7][1], w2.y, a67.y);
        }
        __syncthreads();
    }
    const int n0 = blockIdx.y * 64 + (tx << 2);
    const float bv0 = bih[n0 + 0] + bhh[n0 + 0];
    const float bv1 = bih[n0 + 1] + bhh[n0 + 1];
    const float bv2 = bih[n0 + 2] + bhh[n0 + 2];
    const float bv3 = bih[n0 + 3] + bhh[n0 + 3];
#pragma unroll
    for (int i = 0; i < 8; i++) {
        int m2 = blockIdx.x * 128 + (ty << 3) + i;
        float a0, a1, a2, a3;
        unpack2(acc[i][0], a0, a1);
        unpack2(acc[i][1], a2, a3);
        *reinterpret_cast<float4*>(&g_xg[(size_t)m2 * GG + n0]) =
            make_float4(a0 + bv0, a1 + bv1, a2 + bv2, a3 + bv3);
    }
}

// ---------------- persistent per-layer recurrence kernel ----------------
// 128 CTAs x 128 threads (1/SM). CTA = (hgrp: 8 hids, bgrp: 16 batches).
// Warp = 2 hid x 16 b (warps PARTITION hids -> W_hh read once per CTA, not 4x):
//   wid = tid>>5, lane = tid&31; hid_l = 2*wid + (lane>>4); b_l = lane&15.
__global__ void __launch_bounds__(128, 1) lstm_layer_kernel(const float* __restrict__ Whh,
                                                            float* __restrict__ yext, int layer) {
    extern __shared__ float sm[];
    float* W4 = sm;                  // [8 hid][WSTR] (gate-major within: [gate*256 + k])
    float* hs = sm + 8 * WSTR;       // [16 b][260]
    const int tid = threadIdx.x;
    const int lane = tid & 31;
    const int wid = tid >> 5;
    const int hid_l = (wid << 1) + (lane >> 4);   // 0..7, 2 hids per warp
    const int b_l = lane & 15;                    // 0..15
    const int hgrp = blockIdx.x >> 2;    // 0..31
    const int bgrp = blockIdx.x & 3;     // 0..3
    const int hid = hgrp * 8 + hid_l;
    const int b = bgrp * 16 + b_l;

    // stage W_hh once: W4[hidp][gate*256 + k], gates i,f,g,o
#pragma unroll
    for (int j = 0; j < 16; j++) {
        int f = tid + (j << 7);              // float4 index 0..2047
        int hidp = f >> 8, gate = (f >> 6) & 3, k4 = f & 63;
        float4 v = __ldg(reinterpret_cast<const float4*>(
            Whh + ((size_t)(gate << 8) + (size_t)(hgrp * 8 + hidp)) * HH) + k4);
        *reinterpret_cast<float4*>(W4 + hidp * WSTR + gate * 256 + (k4 << 2)) = v;
    }

    const int mi = b * HH + hid;
    const float mo  = g_masks[(layer * 3 + 0) * BB * HH + mi];
    const float mh  = g_masks[(layer * 3 + 1) * BB * HH + mi];
    const float mcm = g_masks[(layer * 3 + 2) * BB * HH + mi];
    float c = 0.0f;                        // cell state in a register for all 512 steps
    float* y = layer ? yext : g_y0;
    float* yrow = y + (size_t)b * (TT * HH) + hid;
    const float* wbase = W4 + hid_l * WSTR;
    const float* hrow = hs + b_l * 260;

    // prefetch xg(t=0), row-major [t*64+b][4H]
    float xi, xf, xc, xo;
    {
        size_t xb = (size_t)b * GG + hid;
        xi = __ldcs(&g_xg[xb]);
        xf = __ldcs(&g_xg[xb + 256]);
        xc = __ldcs(&g_xg[xb + 512]);
        xo = __ldcs(&g_xg[xb + 768]);
    }
    __syncthreads();   // W4 staged

    for (int t = 0; t < TT; t++) {
        const int cur = t & 1;
        // stage h(t) slice [16 b][256 k]; coalesced LDG.128(.cg) + conflict-free STS.128
        {
            const float4* src = reinterpret_cast<const float4*>(g_hbuf[cur] + (size_t)bgrp * 16 * HH);
#pragma unroll
            for (int j = 0; j < 8; j++) {
                int idx = tid + (j << 7);          // 0..1023 float4s
                float4 v = __ldcg(src + idx);
                int r = idx >> 6, k4 = idx & 63;
                *reinterpret_cast<float4*>(hs + r * 260 + (k4 << 2)) = v;
            }
        }
        __syncthreads();

        // gate dot-products: f32x2 accumulators paired over k
        uint64_t a_i = pack2(xi, 0.0f);
        uint64_t a_f = pack2(xf, 0.0f);
        uint64_t a_c = pack2(xc, 0.0f);
        uint64_t a_o = pack2(xo, 0.0f);
#pragma unroll 8
        for (int k = 0; k < 256; k += 4) {
            ulonglong2 h01 = *reinterpret_cast<const ulonglong2*>(hrow + k);
            ulonglong2 wi = *reinterpret_cast<const ulonglong2*>(wbase + k);
            ulonglong2 wf = *reinterpret_cast<const ulonglong2*>(wbase + 256 + k);
            ulonglong2 wc = *reinterpret_cast<const ulonglong2*>(wbase + 512 + k);
            ulonglong2 wo = *reinterpret_cast<const ulonglong2*>(wbase + 768 + k);
            FFMA2(a_i, wi.x, h01.x); FFMA2(a_i, wi.y, h01.y);
            FFMA2(a_f, wf.x, h01.x); FFMA2(a_f, wf.y, h01.y);
            FFMA2(a_c, wc.x, h01.x); FFMA2(a_c, wc.y, h01.y);
            FFMA2(a_o, wo.x, h01.x); FFMA2(a_o, wo.y, h01.y);
        }
        float gi, gf, gc, go, tmp;
        unpack2(a_i, gi, tmp); gi += tmp;
        unpack2(a_f, gf, tmp); gf += tmp;
        unpack2(a_c, gc, tmp); gc += tmp;
        unpack2(a_o, go, tmp); go += tmp;

        // prefetch next xg before the barrier (hides DRAM latency behind sync)
        if (t + 1 < TT) {
            size_t xb = ((size_t)(t + 1) * BB + b) * GG + hid;
            xi = __ldcs(&g_xg[xb]);
            xf = __ldcs(&g_xg[xb + 256]);
            xc = __ldcs(&g_xg[xb + 512]);
            xo = __ldcs(&g_xg[xb + 768]);
        }

        float i_ = __fdividef(1.0f, 1.0f + __expf(-gi));
        float f_ = __fdividef(1.0f, 1.0f + __expf(-gf));
        float o_ = __fdividef(1.0f, 1.0f + __expf(-go));
        float tg = 1.0f - __fdividef(2.0f, __expf(2.0f * gc) + 1.0f);   // tanh(gc)
        float cn = f_ * c + i_ * tg;
        float th = 1.0f - __fdividef(2.0f, __expf(2.0f * cn) + 1.0f);   // tanh(cn)
        float hn = o_ * th;
        c = cn * mcm;

        yrow[(size_t)t * HH] = hn * mo;
        __stcg(&g_hbuf[cur ^ 1][mi], hn * mh);

        if (t + 1 < TT) {
            __syncthreads();             // all CTA stores precede the release-arrive
            if (tid == 0) {
                red_add_release(&g_bar_arrive, 1u);
                unsigned tgt = (unsigned)(t + 1) * NCTA;
                while (ld_acquire(&g_bar_arrive) < tgt) { }
            }
            __syncthreads();
        }
    }
}

// ---------------- launch (7 graph nodes) ----------------
extern "C" void kernel_launch(void* const* d_in, const int* in_sizes, int n_in,
                              void* d_out, int out_size) {
    const float* x    = (const float*)d_in[0];
    const float* Wih0 = (const float*)d_in[1];
    const float* Whh0 = (const float*)d_in[2];
    const float* bih0 = (const float*)d_in[3];
    const float* bhh0 = (const float*)d_in[4];
    const float* Wih1 = (const float*)d_in[5];
    const float* Whh1 = (const float*)d_in[6];
    const float* bih1 = (const float*)d_in[7];
    const float* bhh1 = (const float*)d_in[8];
    float* out = (float*)d_out;

    const int smem = (8 * WSTR + 16 * 260) * 4;   // (8224 + 4160)*4 = 49536 B
    cudaFuncSetAttribute(lstm_layer_kernel, cudaFuncAttributeMaxDynamicSharedMemorySize, smem);

    compute_masks_kernel<<<(6 * BB * HH + 255) / 256, 256>>>();

    // layer 0
    zero_state_kernel<<<(BB * HH + 255) / 256, 256>>>();
    gemm_xg_kernel<<<dim3((TT * BB) / 128, GG / 64), 256>>>(x, Wih0, bih0, bhh0, 0);
    lstm_layer_kernel<<<NCTA, 128, smem>>>(Whh0, nullptr, 0);

    // layer 1
    zero_state_kernel<<<(BB * HH + 255) / 256, 256>>>();
    gemm_xg_kernel<<<dim3((TT * BB) / 128, GG / 64), 256>>>(nullptr, Wih1, bih1, bhh1, 1);
    lstm_layer_kernel<<<NCTA, 128, smem>>>(Whh1, out, 1);
}

// round 13
// speedup vs baseline: 4.6467x; 1.0253x over previous
#include <cuda_runtime.h>
#include <cstdint>
#include <cstddef>

#define BB 64      // batch
#define TT 512     // time
#define HH 256     // hidden
#define GG 1024    // 4*H
#define NCTA 128   // 32 hid-groups (8 hids) x 4 batch-groups (16 b)
#define NBGRP 4    // independent batch groups (independent barriers)
#define BAR_PER 32 // CTAs per barrier (all hgrps of one bgrp)
#define WSTR 1028  // W smem hid stride (floats): 4112B mod 128B = 16 -> staggered phases

// ---------------- device scratch (static, no allocations) ----------------
__device__ float g_xg[(size_t)TT * BB * GG];   // [t*64+b][4H] row-major gate pre-activations
__device__ float g_y0[(size_t)BB * TT * HH];   // layer-0 output, [B][T][H]
__device__ float g_hbuf[2][BB * HH];           // ping-pong h carry, [b][hid]
__device__ float g_masks[6 * BB * HH];         // (layer,{out,h,c}) masks [B][H]
__device__ unsigned g_bar[NBGRP * 32];         // per-bgrp monotone counters, 128B apart

// ---------------- f32x2 packed math helpers ----------------
__device__ __forceinline__ uint64_t pack2(float lo, float hi) {
    uint64_t r; asm("mov.b64 %0, {%1,%2};" : "=l"(r) : "f"(lo), "f"(hi)); return r;
}
__device__ __forceinline__ void unpack2(uint64_t v, float& lo, float& hi) {
    asm("mov.b64 {%0,%1}, %2;" : "=f"(lo), "=f"(hi) : "l"(v));
}
#define FFMA2(acc, a, b) asm("fma.rn.f32x2 %0, %1, %2, %0;" : "+l"(acc) : "l"(a), "l"(b))

// ---------------- barrier primitives (release/acquire, gpu scope) ----------------
__device__ __forceinline__ void red_add_release(unsigned* p, unsigned v) {
    asm volatile("red.release.gpu.global.add.u32 [%0], %1;" :: "l"(p), "r"(v) : "memory");
}
__device__ __forceinline__ unsigned ld_acquire(const unsigned* p) {
    unsigned v; asm volatile("ld.acquire.gpu.global.u32 %0, [%1];" : "=r"(v) : "l"(p) : "memory");
    return v;
}

// ---------------- Threefry-2x32 (JAX, partitionable) — VALIDATED bit-exact ----------------
__device__ __forceinline__ uint32_t rotl32(uint32_t x, int n) { return __funnelshift_l(x, x, n); }

__device__ __forceinline__ void tf2x32(uint32_t k0, uint32_t k1, uint32_t x0, uint32_t x1,
                                       uint32_t& o0, uint32_t& o1) {
    uint32_t ks2 = k0 ^ k1 ^ 0x1BD11BDAu;
    x0 += k0; x1 += k1;
#define TFR(r) { x0 += x1; x1 = rotl32(x1, (r)); x1 ^= x0; }
    TFR(13) TFR(15) TFR(26) TFR(6)   x0 += k1;  x1 += ks2 + 1u;
    TFR(17) TFR(29) TFR(16) TFR(24)  x0 += ks2; x1 += k0 + 2u;
    TFR(13) TFR(15) TFR(26) TFR(6)   x0 += k0;  x1 += k1 + 3u;
    TFR(17) TFR(29) TFR(16) TFR(24)  x0 += k1;  x1 += ks2 + 4u;
    TFR(13) TFR(15) TFR(26) TFR(6)   x0 += ks2; x1 += k0 + 5u;
#undef TFR
    o0 = x0; o1 = x1;
}

__global__ void compute_masks_kernel() {
    int idx = blockIdx.x * 256 + threadIdx.x;
    if (idx >= 6 * BB * HH) return;
    int l = idx / (3 * BB * HH);
    int j = (idx / (BB * HH)) % 3;
    uint32_t e = (uint32_t)(idx % (BB * HH));
    uint32_t a0, a1, b0, b1, c0, c1;
    tf2x32(0u, 42u, 0u, (uint32_t)l, a0, a1);
    tf2x32(a0, a1, 0u, (uint32_t)j, b0, b1);
    tf2x32(b0, b1, 0u, e, c0, c1);
    uint32_t bits = c0 ^ c1;
    float u = __uint_as_float((bits >> 9) | 0x3f800000u) - 1.0f;
    g_masks[idx] = (u < 0.75f) ? (1.0f / 0.75f) : 0.0f;
}

__global__ void zero_state_kernel() {
    int i = blockIdx.x * 256 + threadIdx.x;
    if (i < BB * HH) {
        g_hbuf[0][i] = 0.0f;
        g_hbuf[1][i] = 0.0f;
    }
    if (i < NBGRP * 32) g_bar[i] = 0u;   // reset per layer / per replay (determinism)
}

// ---------------- big GEMM (f32x2, double-buffered, LDS.128 A-feed) — unchanged r9 ----------------
__global__ void __launch_bounds__(256) gemm_xg_kernel(const float* __restrict__ Aext,
                                                      const float* __restrict__ W,
                                                      const float* __restrict__ bih,
                                                      const float* __restrict__ bhh,
                                                      int use_y0) {
    const float* A = use_y0 ? g_y0 : Aext;
    __shared__ uint64_t As2[16][132];   // (a,a) dup pairs, [k][m]
    __shared__ float Bs[16][68];        // [k][n]
    const int tid = threadIdx.x;
    const int arow_l = tid >> 1;
    const int ak = (tid & 1) << 3;
    const int m = blockIdx.x * 128 + arow_l;
    const float* Arow = A + ((size_t)(m & 63) * TT + (size_t)(m >> 6)) * HH;
    const int brow_l = tid >> 2;
    const int bk = (tid & 3) << 2;
    const float* Wrow = W + (size_t)(blockIdx.y * 64 + brow_l) * HH;
    const int tx = tid & 15, ty = tid >> 4;

    uint64_t acc[8][2];
#pragma unroll
    for (int i = 0; i < 8; i++) { acc[i][0] = 0ull; acc[i][1] = 0ull; }

    float4 a0v = *reinterpret_cast<const float4*>(Arow + ak);
    float4 a1v = *reinterpret_cast<const float4*>(Arow + ak + 4);
    float4 bv  = *reinterpret_cast<const float4*>(Wrow + bk);

    for (int k0 = 0; k0 < 256; k0 += 16) {
        As2[ak + 0][arow_l] = pack2(a0v.x, a0v.x);
        As2[ak + 1][arow_l] = pack2(a0v.y, a0v.y);
        As2[ak + 2][arow_l] = pack2(a0v.z, a0v.z);
        As2[ak + 3][arow_l] = pack2(a0v.w, a0v.w);
        As2[ak + 4][arow_l] = pack2(a1v.x, a1v.x);
        As2[ak + 5][arow_l] = pack2(a1v.y, a1v.y);
        As2[ak + 6][arow_l] = pack2(a1v.z, a1v.z);
        As2[ak + 7][arow_l] = pack2(a1v.w, a1v.w);
        Bs[bk + 0][brow_l] = bv.x;
        Bs[bk + 1][brow_l] = bv.y;
        Bs[bk + 2][brow_l] = bv.z;
        Bs[bk + 3][brow_l] = bv.w;
        __syncthreads();
        if (k0 + 16 < 256) {   // overlap next tile's LDGs with this tile's FFMA2 burst
            a0v = *reinterpret_cast<const float4*>(Arow + k0 + 16 + ak);
            a1v = *reinterpret_cast<const float4*>(Arow + k0 + 16 + ak + 4);
            bv  = *reinterpret_cast<const float4*>(Wrow + k0 + 16 + bk);
        }
#pragma unroll
        for (int kk = 0; kk < 16; kk++) {
            ulonglong2 w2 = *reinterpret_cast<const ulonglong2*>(&Bs[kk][tx << 2]);
            const ulonglong2* ap = reinterpret_cast<const ulonglong2*>(&As2[kk][ty << 3]);
            ulonglong2 a01 = ap[0];
            ulonglong2 a23 = ap[1];
            ulonglong2 a45 = ap[2];
            ulonglong2 a67 = ap[3];
            FFMA2(acc[0][0], w2.x, a01.x); FFMA2(acc[0][1], w2.y, a01.x);
            FFMA2(acc[1][0], w2.x, a01.y); FFMA2(acc[1][1], w2.y, a01.y);
            FFMA2(acc[2][0], w2.x, a23.x); FFMA2(acc[2][1], w2.y, a23.x);
            FFMA2(acc[3][0], w2.x, a23.y); FFMA2(acc[3][1], w2.y, a23.y);
            FFMA2(acc[4][0], w2.x, a45.x); FFMA2(acc[4][1], w2.y, a45.x);
            FFMA2(acc[5][0], w2.x, a45.y); FFMA2(acc[5][1], w2.y, a45.y);
            FFMA2(acc[6][0], w2.x, a67.x); FFMA2(acc[6][1], w2.y, a67.x);
            FFMA2(acc[7][0], w2.x, a67.y); FFMA2(acc[7][1], w2.y, a67.y);
        }
        __syncthreads();
    }
    const int n0 = blockIdx.y * 64 + (tx << 2);
    const float bv0 = bih[n0 + 0] + bhh[n0 + 0];
    const float bv1 = bih[n0 + 1] + bhh[n0 + 1];
    const float bv2 = bih[n0 + 2] + bhh[n0 + 2];
    const float bv3 = bih[n0 + 3] + bhh[n0 + 3];
#pragma unroll
    for (int i = 0; i < 8; i++) {
        int m2 = blockIdx.x * 128 + (ty << 3) + i;
        float a0, a1, a2, a3;
        unpack2(acc[i][0], a0, a1);
        unpack2(acc[i][1], a2, a3);
        *reinterpret_cast<float4*>(&g_xg[(size_t)m2 * GG + n0]) =
            make_float4(a0 + bv0, a1 + bv1, a2 + bv2, a3 + bv3);
    }
}

// ---------------- persistent per-layer recurrence kernel ----------------
// 128 CTAs x 128 threads (1/SM). CTA = (hgrp: 8 hids, bgrp: 16 batches).
// Warp = 2 hid x 16 b. Cross-bgrp: ZERO data flow -> 4 independent 32-CTA barriers,
// so batch groups pipeline independently and stragglers couple only within 32 CTAs.
__global__ void __launch_bounds__(128, 1) lstm_layer_kernel(const float* __restrict__ Whh,
                                                            float* __restrict__ yext, int layer) {
    extern __shared__ float sm[];
    float* W4 = sm;                  // [8 hid][WSTR] (gate-major within: [gate*256 + k])
    float* hs = sm + 8 * WSTR;       // [16 b][260]
    const int tid = threadIdx.x;
    const int lane = tid & 31;
    const int wid = tid >> 5;
    const int hid_l = (wid << 1) + (lane >> 4);   // 0..7, 2 hids per warp
    const int b_l = lane & 15;                    // 0..15
    const int hgrp = blockIdx.x >> 2;    // 0..31
    const int bgrp = blockIdx.x & 3;     // 0..3
    const int hid = hgrp * 8 + hid_l;
    const int b = bgrp * 16 + b_l;
    unsigned* barp = &g_bar[bgrp * 32];  // this bgrp's counter (own 128B line)

    // stage W_hh once: W4[hidp][gate*256 + k], gates i,f,g,o
#pragma unroll
    for (int j = 0; j < 16; j++) {
        int f = tid + (j << 7);              // float4 index 0..2047
        int hidp = f >> 8, gate = (f >> 6) & 3, k4 = f & 63;
        float4 v = __ldg(reinterpret_cast<const float4*>(
            Whh + ((size_t)(gate << 8) + (size_t)(hgrp * 8 + hidp)) * HH) + k4);
        *reinterpret_cast<float4*>(W4 + hidp * WSTR + gate * 256 + (k4 << 2)) = v;
    }

    const int mi = b * HH + hid;
    const float mo  = g_masks[(layer * 3 + 0) * BB * HH + mi];
    const float mh  = g_masks[(layer * 3 + 1) * BB * HH + mi];
    const float mcm = g_masks[(layer * 3 + 2) * BB * HH + mi];
    float c = 0.0f;                        // cell state in a register for all 512 steps
    float* y = layer ? yext : g_y0;
    float* yrow = y + (size_t)b * (TT * HH) + hid;
    const float* wbase = W4 + hid_l * WSTR;
    const float* hrow = hs + b_l * 260;

    // prefetch xg(t=0), row-major [t*64+b][4H]
    float xi, xf, xc, xo;
    {
        size_t xb = (size_t)b * GG + hid;
        xi = __ldcs(&g_xg[xb]);
        xf = __ldcs(&g_xg[xb + 256]);
        xc = __ldcs(&g_xg[xb + 512]);
        xo = __ldcs(&g_xg[xb + 768]);
    }
    __syncthreads();   // W4 staged

    for (int t = 0; t < TT; t++) {
        const int cur = t & 1;
        // stage h(t) slice [16 b][256 k]; coalesced LDG.128(.cg) + conflict-free STS.128
        {
            const float4* src = reinterpret_cast<const float4*>(g_hbuf[cur] + (size_t)bgrp * 16 * HH);
#pragma unroll
            for (int j = 0; j < 8; j++) {
                int idx = tid + (j << 7);          // 0..1023 float4s
                float4 v = __ldcg(src + idx);
                int r = idx >> 6, k4 = idx & 63;
                *reinterpret_cast<float4*>(hs + r * 260 + (k4 << 2)) = v;
            }
        }
        __syncthreads();

        // gate dot-products: f32x2 accumulators paired over k
        uint64_t a_i = pack2(xi, 0.0f);
        uint64_t a_f = pack2(xf, 0.0f);
        uint64_t a_c = pack2(xc, 0.0f);
        uint64_t a_o = pack2(xo, 0.0f);
#pragma unroll 8
        for (int k = 0; k < 256; k += 4) {
            ulonglong2 h01 = *reinterpret_cast<const ulonglong2*>(hrow + k);
            ulonglong2 wi = *reinterpret_cast<const ulonglong2*>(wbase + k);
            ulonglong2 wf = *reinterpret_cast<const ulonglong2*>(wbase + 256 + k);
            ulonglong2 wc = *reinterpret_cast<const ulonglong2*>(wbase + 512 + k);
            ulonglong2 wo = *reinterpret_cast<const ulonglong2*>(wbase + 768 + k);
            FFMA2(a_i, wi.x, h01.x); FFMA2(a_i, wi.y, h01.y);
            FFMA2(a_f, wf.x, h01.x); FFMA2(a_f, wf.y, h01.y);
            FFMA2(a_c, wc.x, h01.x); FFMA2(a_c, wc.y, h01.y);
            FFMA2(a_o, wo.x, h01.x); FFMA2(a_o, wo.y, h01.y);
        }
        float gi, gf, gc, go, tmp;
        unpack2(a_i, gi, tmp); gi += tmp;
        unpack2(a_f, gf, tmp); gf += tmp;
        unpack2(a_c, gc, tmp); gc += tmp;
        unpack2(a_o, go, tmp); go += tmp;

        // prefetch next xg before the barrier (hides DRAM latency behind sync)
        if (t + 1 < TT) {
            size_t xb = ((size_t)(t + 1) * BB + b) * GG + hid;
            xi = __ldcs(&g_xg[xb]);
            xf = __ldcs(&g_xg[xb + 256]);
            xc = __ldcs(&g_xg[xb + 512]);
            xo = __ldcs(&g_xg[xb + 768]);
        }

        float i_ = __fdividef(1.0f, 1.0f + __expf(-gi));
        float f_ = __fdividef(1.0f, 1.0f + __expf(-gf));
        float o_ = __fdividef(1.0f, 1.0f + __expf(-go));
        float tg = 1.0f - __fdividef(2.0f, __expf(2.0f * gc) + 1.0f);   // tanh(gc)
        float cn = f_ * c + i_ * tg;
        float th = 1.0f - __fdividef(2.0f, __expf(2.0f * cn) + 1.0f);   // tanh(cn)
        float hn = o_ * th;
        c = cn * mcm;

        // critical path first: the h the next step waits on
        __stcg(&g_hbuf[cur ^ 1][mi], hn * mh);
        yrow[(size_t)t * HH] = hn * mo;

        if (t + 1 < TT) {
            __syncthreads();             // all CTA stores precede the release-arrive
            if (tid == 0) {
                red_add_release(barp, 1u);
                unsigned tgt = (unsigned)(t + 1) * BAR_PER;
                while (ld_acquire(barp) < tgt) { }
            }
            __syncthreads();
        }
    }
}

// ---------------- launch (7 graph nodes) ----------------
extern "C" void kernel_launch(void* const* d_in, const int* in_sizes, int n_in,
                              void* d_out, int out_size) {
    const float* x    = (const float*)d_in[0];
    const float* Wih0 = (const float*)d_in[1];
    const float* Whh0 = (const float*)d_in[2];
    const float* bih0 = (const float*)d_in[3];
    const float* bhh0 = (const float*)d_in[4];
    const float* Wih1 = (const float*)d_in[5];
    const float* Whh1 = (const float*)d_in[6];
    const float* bih1 = (const float*)d_in[7];
    const float* bhh1 = (const float*)d_in[8];
    float* out = (float*)d_out;

    const int smem = (8 * WSTR + 16 * 260) * 4;   // (8224 + 4160)*4 = 49536 B
    cudaFuncSetAttribute(lstm_layer_kernel, cudaFuncAttributeMaxDynamicSharedMemorySize, smem);

    compute_masks_kernel<<<(6 * BB * HH + 255) / 256, 256>>>();

    // layer 0
    zero_state_kernel<<<(BB * HH + 255) / 256, 256>>>();
    gemm_xg_kernel<<<dim3((TT * BB) / 128, GG / 64), 256>>>(x, Wih0, bih0, bhh0, 0);
    lstm_layer_kernel<<<NCTA, 128, smem>>>(Whh0, nullptr, 0);

    // layer 1
    zero_state_kernel<<<(BB * HH + 255) / 256, 256>>>();
    gemm_xg_kernel<<<dim3((TT * BB) / 128, GG / 64), 256>>>(nullptr, Wih1, bih1, bhh1, 1);
    lstm_layer_kernel<<<NCTA, 128, smem>>>(Whh1, out, 1);
}